// round 1
// baseline (speedup 1.0000x reference)
#include <cuda_runtime.h>
#include <cuda_bf16.h>
#include <cstdint>

#define NN 100000
#define EE 1600000
#define NE_TOT (EE + NN)          // edges incl. self loops
#define H4 4
#define C1 16
#define HC1 64                     // H*C1 (layer1 per-node feat)
#define NOUT 64
#define HN2 256                    // H*NOUT (layer2 per-node feat)
#define NEG_SLOPE 0.2f

// ---------------- scratch (device globals; no allocation allowed) ----------
__device__ float g_xl1[(size_t)NN * HC1];
__device__ float g_xr1[(size_t)NN * HC1];
__device__ float g_h  [(size_t)NN * HC1];
__device__ float g_xl2[(size_t)NN * HN2];
__device__ float g_xr2[(size_t)NN * HN2];
__device__ float g_acc1[(size_t)NN * HC1];
__device__ float g_acc2[(size_t)NN * HN2];
__device__ float g_den1[(size_t)NN * H4];
__device__ float g_den2[(size_t)NN * H4];
__device__ int   g_eidx[2 * EE];
__device__ int   g_is64;

// ---------------- edge-index dtype detection + normalization ---------------
__global__ void detect_kernel(const void* p) {
    if (threadIdx.x == 0 && blockIdx.x == 0) {
        const long long* q = (const long long*)p;
        int is64 = 1;
        for (int i = 0; i < 256; i++) {
            long long v = q[i];
            if (v < 0 || v >= NN) { is64 = 0; break; }
        }
        g_is64 = is64;
    }
}

__global__ void convert_edges(const void* p) {
    int idx = blockIdx.x * blockDim.x + threadIdx.x;
    if (idx >= 2 * EE) return;
    int v;
    if (g_is64) v = (int)((const long long*)p)[idx];
    else        v = ((const int*)p)[idx];
    g_eidx[idx] = v;
}

// ---------------- zero accumulators ----------------------------------------
__global__ void zero_kernel() {
    size_t stride = (size_t)gridDim.x * blockDim.x;
    size_t idx = (size_t)blockIdx.x * blockDim.x + threadIdx.x;
    for (size_t t = idx; t < (size_t)NN * HC1; t += stride) g_acc1[t] = 0.f;
    for (size_t t = idx; t < (size_t)NN * HN2; t += stride) g_acc2[t] = 0.f;
    for (size_t t = idx; t < (size_t)NN * H4;  t += stride) { g_den1[t] = 0.f; g_den2[t] = 0.f; }
}

// ---------------- GEMM: Y[n x M] = X[n x 64] @ W[64 x M] + B ---------------
// 64x64 block tile, 256 threads, 4x4 thread tile.
__global__ __launch_bounds__(256) void gemm_bias(
    const float* __restrict__ X, const float* __restrict__ W,
    const float* __restrict__ B, float* __restrict__ Y, int n, int M)
{
    __shared__ float xs[64][68];   // [k][node], padded, 16B-aligned rows
    __shared__ float ws[64][64];   // [k][m]
    const int n0 = blockIdx.x * 64;
    const int m0 = blockIdx.y * 64;
    const int tid = threadIdx.x;

    #pragma unroll
    for (int it = 0; it < 16; it++) {
        int idx = tid + it * 256;
        int k = idx & 63, r = idx >> 6;
        int node = n0 + r;
        xs[k][r] = (node < n) ? X[(size_t)node * 64 + k] : 0.f;
    }
    #pragma unroll
    for (int it = 0; it < 16; it++) {
        int idx = tid + it * 256;
        int mm = idx & 63, k = idx >> 6;
        ws[k][mm] = W[(size_t)k * M + m0 + mm];
    }
    __syncthreads();

    const int tx = tid & 15, ty = tid >> 4;
    float acc[4][4] = {};
    #pragma unroll
    for (int k = 0; k < 64; k++) {
        float4 a = *(const float4*)&xs[k][ty * 4];
        float4 b = *(const float4*)&ws[k][tx * 4];
        acc[0][0] = fmaf(a.x, b.x, acc[0][0]); acc[0][1] = fmaf(a.x, b.y, acc[0][1]);
        acc[0][2] = fmaf(a.x, b.z, acc[0][2]); acc[0][3] = fmaf(a.x, b.w, acc[0][3]);
        acc[1][0] = fmaf(a.y, b.x, acc[1][0]); acc[1][1] = fmaf(a.y, b.y, acc[1][1]);
        acc[1][2] = fmaf(a.y, b.z, acc[1][2]); acc[1][3] = fmaf(a.y, b.w, acc[1][3]);
        acc[2][0] = fmaf(a.z, b.x, acc[2][0]); acc[2][1] = fmaf(a.z, b.y, acc[2][1]);
        acc[2][2] = fmaf(a.z, b.z, acc[2][2]); acc[2][3] = fmaf(a.z, b.w, acc[2][3]);
        acc[3][0] = fmaf(a.w, b.x, acc[3][0]); acc[3][1] = fmaf(a.w, b.y, acc[3][1]);
        acc[3][2] = fmaf(a.w, b.z, acc[3][2]); acc[3][3] = fmaf(a.w, b.w, acc[3][3]);
    }
    float4 bb = *(const float4*)&B[m0 + tx * 4];
    #pragma unroll
    for (int i = 0; i < 4; i++) {
        int node = n0 + ty * 4 + i;
        if (node < n) {
            float4 o;
            o.x = acc[i][0] + bb.x; o.y = acc[i][1] + bb.y;
            o.z = acc[i][2] + bb.z; o.w = acc[i][3] + bb.w;
            *(float4*)&Y[(size_t)node * M + m0 + tx * 4] = o;
        }
    }
}

__device__ __forceinline__ float lrelu(float v) { return v > 0.f ? v : NEG_SLOPE * v; }

// ---------------- layer-1 edge pass: one warp per edge ---------------------
__global__ __launch_bounds__(256) void edge1_kernel(const float* __restrict__ att) {
    int warp = (blockIdx.x * 256 + threadIdx.x) >> 5;
    if (warp >= NE_TOT) return;
    int lane = threadIdx.x & 31;
    int s, d;
    if (warp < EE) { s = g_eidx[warp]; d = g_eidx[EE + warp]; }
    else           { s = warp - EE; d = s; }
    int c0 = lane * 2;
    float2 xl = *(const float2*)(g_xl1 + (size_t)s * HC1 + c0);
    float2 xr = *(const float2*)(g_xr1 + (size_t)d * HC1 + c0);
    float e0 = lrelu(xl.x + xr.x);
    float e1 = lrelu(xl.y + xr.y);
    float p = fmaf(att[c0], e0, att[c0 + 1] * e1);
    // reduce within 8-lane groups (16 channels per head, 2 per lane)
    p += __shfl_xor_sync(0xffffffffu, p, 4);
    p += __shfl_xor_sync(0xffffffffu, p, 2);
    p += __shfl_xor_sync(0xffffffffu, p, 1);
    float ex = __expf(p);
    if ((lane & 7) == 0) atomicAdd(g_den1 + (size_t)d * H4 + (lane >> 3), ex);
    atomicAdd(g_acc1 + (size_t)d * HC1 + c0,     ex * xl.x);
    atomicAdd(g_acc1 + (size_t)d * HC1 + c0 + 1, ex * xl.y);
}

// ---------------- layer-1 finalize: h = relu(acc/den + bo1) ----------------
__global__ __launch_bounds__(256) void finalize1_kernel(const float* __restrict__ bo) {
    int idx = blockIdx.x * 256 + threadIdx.x;
    if (idx >= NN * HC1) return;
    int i = idx >> 6, j = idx & 63, h = j >> 4;
    float v = g_acc1[idx] / (g_den1[i * H4 + h] + 1e-16f) + bo[j];
    g_h[idx] = v > 0.f ? v : 0.f;
}

// ---------------- layer-2 edge pass: one warp per (edge, head) -------------
__global__ __launch_bounds__(256) void edge2_kernel(const float* __restrict__ att) {
    int warp = (blockIdx.x * 256 + threadIdx.x) >> 5;
    if (warp >= NE_TOT * H4) return;
    int e = warp >> 2, h = warp & 3;
    int lane = threadIdx.x & 31;
    int s, d;
    if (e < EE) { s = g_eidx[e]; d = g_eidx[EE + e]; }
    else        { s = e - EE; d = s; }
    int c0 = lane * 2;
    size_t sb = (size_t)s * HN2 + h * NOUT + c0;
    size_t db = (size_t)d * HN2 + h * NOUT + c0;
    float2 xl = *(const float2*)(g_xl2 + sb);
    float2 xr = *(const float2*)(g_xr2 + db);
    float e0 = lrelu(xl.x + xr.x);
    float e1 = lrelu(xl.y + xr.y);
    float p = fmaf(att[h * NOUT + c0], e0, att[h * NOUT + c0 + 1] * e1);
    p += __shfl_xor_sync(0xffffffffu, p, 16);
    p += __shfl_xor_sync(0xffffffffu, p, 8);
    p += __shfl_xor_sync(0xffffffffu, p, 4);
    p += __shfl_xor_sync(0xffffffffu, p, 2);
    p += __shfl_xor_sync(0xffffffffu, p, 1);
    float ex = __expf(p);
    if (lane == 0) atomicAdd(g_den2 + (size_t)d * H4 + h, ex);
    atomicAdd(g_acc2 + db,     ex * xl.x);
    atomicAdd(g_acc2 + db + 1, ex * xl.y);
}

// ---------------- layer-2 finalize: mean over heads, +bo2, relu ------------
__global__ __launch_bounds__(256) void finalize2_kernel(const float* __restrict__ bo,
                                                        float* __restrict__ out) {
    int idx = blockIdx.x * 256 + threadIdx.x;
    if (idx >= NN * NOUT) return;
    int i = idx >> 6, c = idx & 63;
    float s = 0.f;
    #pragma unroll
    for (int h = 0; h < H4; h++)
        s += g_acc2[(size_t)i * HN2 + h * NOUT + c] / (g_den2[i * H4 + h] + 1e-16f);
    float v = 0.25f * s + bo[c];
    out[idx] = v > 0.f ? v : 0.f;
}

// ---------------- host orchestration ---------------------------------------
extern "C" void kernel_launch(void* const* d_in, const int* in_sizes, int n_in,
                              void* d_out, int out_size) {
    const float* x    = (const float*)d_in[0];
    const void*  ei   = d_in[1];
    // d_in[2] = frame_mask (unused by reference)
    const float* Wl1  = (const float*)d_in[3];
    const float* bl1  = (const float*)d_in[4];
    const float* Wr1  = (const float*)d_in[5];
    const float* br1  = (const float*)d_in[6];
    const float* att1 = (const float*)d_in[7];
    const float* bo1  = (const float*)d_in[8];
    const float* Wl2  = (const float*)d_in[9];
    const float* bl2  = (const float*)d_in[10];
    const float* Wr2  = (const float*)d_in[11];
    const float* br2  = (const float*)d_in[12];
    const float* att2 = (const float*)d_in[13];
    const float* bo2  = (const float*)d_in[14];
    float* out = (float*)d_out;

    float *p_xl1, *p_xr1, *p_h, *p_xl2, *p_xr2;
    cudaGetSymbolAddress((void**)&p_xl1, g_xl1);
    cudaGetSymbolAddress((void**)&p_xr1, g_xr1);
    cudaGetSymbolAddress((void**)&p_h,   g_h);
    cudaGetSymbolAddress((void**)&p_xl2, g_xl2);
    cudaGetSymbolAddress((void**)&p_xr2, g_xr2);

    const int nblk = (NN + 63) / 64;   // 1563

    detect_kernel<<<1, 32>>>(ei);
    convert_edges<<<(2 * EE + 255) / 256, 256>>>(ei);
    zero_kernel<<<2048, 256>>>();

    gemm_bias<<<dim3(nblk, 1), 256>>>(x, Wl1, bl1, p_xl1, NN, HC1);
    gemm_bias<<<dim3(nblk, 1), 256>>>(x, Wr1, br1, p_xr1, NN, HC1);

    edge1_kernel<<<(NE_TOT * 32 + 255) / 256, 256>>>(att1);
    finalize1_kernel<<<(NN * HC1 + 255) / 256, 256>>>(bo1);

    gemm_bias<<<dim3(nblk, 4), 256>>>(p_h, Wl2, bl2, p_xl2, NN, HN2);
    gemm_bias<<<dim3(nblk, 4), 256>>>(p_h, Wr2, br2, p_xr2, NN, HN2);

    edge2_kernel<<<(NE_TOT * 4 * 32 + 255) / 256, 256>>>(att2);
    finalize2_kernel<<<(NN * NOUT + 255) / 256, 256>>>(bo2, out);
}

// round 2
// speedup vs baseline: 2.1538x; 2.1538x over previous
#include <cuda_runtime.h>
#include <cuda_fp16.h>
#include <cstdint>

#define NN 100000
#define EE 1600000
#define NE_TOT (EE + NN)          // edges incl. self loops
#define H4 4
#define HC1 64                     // H*C1 (layer1 per-node feat)
#define NOUT 64
#define HN2 256                    // H*NOUT (layer2 per-node feat)
#define NEG_SLOPE 0.2f

// ---------------- scratch (device globals; no allocation allowed) ----------
__device__ __half g_xl1h[(size_t)NN * HC1];
__device__ __half g_xr1h[(size_t)NN * HC1];
__device__ float  g_h   [(size_t)NN * HC1];
__device__ __half g_xl2h[(size_t)NN * HN2];
__device__ __half g_xr2h[(size_t)NN * HN2];
__device__ int    g_eidx[2 * EE];
__device__ int    g_is64;
__device__ int    g_deg[NN];
__device__ int    g_rs [NN + 1];
__device__ int    g_cur[NN];
__device__ int    g_csr[NE_TOT];

// ---------------- edge-index dtype detection + normalization ---------------
__global__ void detect_kernel(const void* p) {
    if (threadIdx.x == 0 && blockIdx.x == 0) {
        const long long* q = (const long long*)p;
        int is64 = 1;
        for (int i = 0; i < 256; i++) {
            long long v = q[i];
            if (v < 0 || v >= NN) { is64 = 0; break; }
        }
        g_is64 = is64;
    }
}

__global__ void convert_edges(const void* p) {
    int idx = blockIdx.x * blockDim.x + threadIdx.x;
    if (idx >= 2 * EE) return;
    int v;
    if (g_is64) v = (int)((const long long*)p)[idx];
    else        v = ((const int*)p)[idx];
    g_eidx[idx] = v;
}

// ---------------- CSR build -------------------------------------------------
__global__ void zero_deg_kernel() {
    int i = blockIdx.x * blockDim.x + threadIdx.x;
    if (i < NN) g_deg[i] = 0;
}

__global__ void hist_kernel() {
    int idx = blockIdx.x * blockDim.x + threadIdx.x;
    if (idx >= NE_TOT) return;
    int d = (idx < EE) ? g_eidx[EE + idx] : (idx - EE);
    atomicAdd(g_deg + d, 1);
}

// single-block exclusive scan of g_deg -> g_rs, copy to g_cur
__global__ __launch_bounds__(1024) void scan_kernel() {
    const int CH = (NN + 1023) / 1024;     // 98
    int t = threadIdx.x;
    int lo = t * CH, hi = lo + CH; if (hi > NN) hi = NN;
    int s = 0;
    for (int k = lo; k < hi; k++) s += g_deg[k];
    __shared__ int sums[1024];
    sums[t] = s; __syncthreads();
    for (int off = 1; off < 1024; off <<= 1) {
        int v = (t >= off) ? sums[t - off] : 0;
        __syncthreads();
        sums[t] += v;
        __syncthreads();
    }
    int run = sums[t] - s;                 // exclusive prefix for this chunk
    for (int k = lo; k < hi; k++) {
        g_rs[k] = run; g_cur[k] = run;
        run += g_deg[k];
    }
    if (t == 1023) g_rs[NN] = sums[1023];
}

__global__ void scatter_kernel() {
    int idx = blockIdx.x * blockDim.x + threadIdx.x;
    if (idx >= NE_TOT) return;
    int s, d;
    if (idx < EE) { s = g_eidx[idx]; d = g_eidx[EE + idx]; }
    else          { s = idx - EE; d = s; }
    int pos = atomicAdd(g_cur + d, 1);
    g_csr[pos] = s;
}

// ---------------- GEMM: Y[n x M](half) = X[n x 64] @ W[64 x M] + B ---------
__global__ __launch_bounds__(256) void gemm_bias_h(
    const float* __restrict__ X, const float* __restrict__ W,
    const float* __restrict__ B, __half* __restrict__ Y, int n, int M)
{
    __shared__ float xs[64][68];
    __shared__ float ws[64][64];
    const int n0 = blockIdx.x * 64;
    const int m0 = blockIdx.y * 64;
    const int tid = threadIdx.x;

    #pragma unroll
    for (int it = 0; it < 16; it++) {
        int idx = tid + it * 256;
        int k = idx & 63, r = idx >> 6;
        int node = n0 + r;
        xs[k][r] = (node < n) ? X[(size_t)node * 64 + k] : 0.f;
    }
    #pragma unroll
    for (int it = 0; it < 16; it++) {
        int idx = tid + it * 256;
        int mm = idx & 63, k = idx >> 6;
        ws[k][mm] = W[(size_t)k * M + m0 + mm];
    }
    __syncthreads();

    const int tx = tid & 15, ty = tid >> 4;
    float acc[4][4] = {};
    #pragma unroll
    for (int k = 0; k < 64; k++) {
        float4 a = *(const float4*)&xs[k][ty * 4];
        float4 b = *(const float4*)&ws[k][tx * 4];
        acc[0][0] = fmaf(a.x, b.x, acc[0][0]); acc[0][1] = fmaf(a.x, b.y, acc[0][1]);
        acc[0][2] = fmaf(a.x, b.z, acc[0][2]); acc[0][3] = fmaf(a.x, b.w, acc[0][3]);
        acc[1][0] = fmaf(a.y, b.x, acc[1][0]); acc[1][1] = fmaf(a.y, b.y, acc[1][1]);
        acc[1][2] = fmaf(a.y, b.z, acc[1][2]); acc[1][3] = fmaf(a.y, b.w, acc[1][3]);
        acc[2][0] = fmaf(a.z, b.x, acc[2][0]); acc[2][1] = fmaf(a.z, b.y, acc[2][1]);
        acc[2][2] = fmaf(a.z, b.z, acc[2][2]); acc[2][3] = fmaf(a.z, b.w, acc[2][3]);
        acc[3][0] = fmaf(a.w, b.x, acc[3][0]); acc[3][1] = fmaf(a.w, b.y, acc[3][1]);
        acc[3][2] = fmaf(a.w, b.z, acc[3][2]); acc[3][3] = fmaf(a.w, b.w, acc[3][3]);
    }
    float4 bb = *(const float4*)&B[m0 + tx * 4];
    #pragma unroll
    for (int i = 0; i < 4; i++) {
        int node = n0 + ty * 4 + i;
        if (node < n) {
            size_t off = (size_t)node * M + m0 + tx * 4;
            __half2 h0 = __floats2half2_rn(acc[i][0] + bb.x, acc[i][1] + bb.y);
            __half2 h1 = __floats2half2_rn(acc[i][2] + bb.z, acc[i][3] + bb.w);
            *(__half2*)&Y[off]     = h0;
            *(__half2*)&Y[off + 2] = h1;
        }
    }
}

__device__ __forceinline__ float lrelu(float v) { return v > 0.f ? v : NEG_SLOPE * v; }

// ---------------- layer-1: one warp per node (CSR, atomic-free) -------------
__global__ __launch_bounds__(256) void edge1_node_kernel(
    const float* __restrict__ att, const float* __restrict__ bo)
{
    int node = (blockIdx.x * 256 + threadIdx.x) >> 5;
    if (node >= NN) return;
    int lane = threadIdx.x & 31;
    int c0 = lane * 2;

    float2 xr = __half22float2(*(const __half2*)(g_xr1h + (size_t)node * HC1 + c0));
    float  a0 = att[c0], a1 = att[c0 + 1];

    float accx = 0.f, accy = 0.f, den = 0.f;
    int rs = g_rs[node], re = g_rs[node + 1];
    for (int base = rs; base < re; base += 32) {
        int m = re - base;
        int sj = (lane < m) ? g_csr[base + lane] : 0;
        int jmax = (m < 32) ? m : 32;
        for (int j = 0; j < jmax; j++) {
            int s = __shfl_sync(0xffffffffu, sj, j);
            float2 xl = __half22float2(*(const __half2*)(g_xl1h + (size_t)s * HC1 + c0));
            float e0 = lrelu(xl.x + xr.x);
            float e1 = lrelu(xl.y + xr.y);
            float p = fmaf(a0, e0, a1 * e1);
            p += __shfl_xor_sync(0xffffffffu, p, 4);
            p += __shfl_xor_sync(0xffffffffu, p, 2);
            p += __shfl_xor_sync(0xffffffffu, p, 1);
            float ex = __expf(p);
            accx = fmaf(ex, xl.x, accx);
            accy = fmaf(ex, xl.y, accy);
            den += ex;
        }
    }
    float inv = 1.f / (den + 1e-16f);
    float v0 = accx * inv + bo[c0];
    float v1 = accy * inv + bo[c0 + 1];
    size_t o = (size_t)node * HC1 + c0;
    g_h[o]     = v0 > 0.f ? v0 : 0.f;
    g_h[o + 1] = v1 > 0.f ? v1 : 0.f;
}

// ---------------- layer-2: one block (128 thr) per node, warp = head --------
__global__ __launch_bounds__(128) void edge2_node_kernel(
    const float* __restrict__ att, const float* __restrict__ bo,
    float* __restrict__ out)
{
    int node = blockIdx.x;
    int tid = threadIdx.x;
    int head = tid >> 5;
    int lane = tid & 31;
    int c0 = lane * 2;
    int hb = head * NOUT;

    float2 xr = __half22float2(*(const __half2*)(g_xr2h + (size_t)node * HN2 + hb + c0));
    float  a0 = att[hb + c0], a1 = att[hb + c0 + 1];

    float accx = 0.f, accy = 0.f, den = 0.f;
    int rs = g_rs[node], re = g_rs[node + 1];
    for (int base = rs; base < re; base += 32) {
        int m = re - base;
        int sj = (lane < m) ? g_csr[base + lane] : 0;
        int jmax = (m < 32) ? m : 32;
        for (int j = 0; j < jmax; j++) {
            int s = __shfl_sync(0xffffffffu, sj, j);
            float2 xl = __half22float2(*(const __half2*)(g_xl2h + (size_t)s * HN2 + hb + c0));
            float e0 = lrelu(xl.x + xr.x);
            float e1 = lrelu(xl.y + xr.y);
            float p = fmaf(a0, e0, a1 * e1);
            p += __shfl_xor_sync(0xffffffffu, p, 16);
            p += __shfl_xor_sync(0xffffffffu, p, 8);
            p += __shfl_xor_sync(0xffffffffu, p, 4);
            p += __shfl_xor_sync(0xffffffffu, p, 2);
            p += __shfl_xor_sync(0xffffffffu, p, 1);
            float ex = __expf(p);
            accx = fmaf(ex, xl.x, accx);
            accy = fmaf(ex, xl.y, accy);
            den += ex;
        }
    }
    __shared__ float red[H4][NOUT];
    float inv = 1.f / (den + 1e-16f);
    red[head][c0]     = accx * inv;
    red[head][c0 + 1] = accy * inv;
    __syncthreads();
    if (tid < NOUT) {
        float sum = red[0][tid] + red[1][tid] + red[2][tid] + red[3][tid];
        float v = 0.25f * sum + bo[tid];
        out[(size_t)node * NOUT + tid] = v > 0.f ? v : 0.f;
    }
}

// ---------------- host orchestration ---------------------------------------
extern "C" void kernel_launch(void* const* d_in, const int* in_sizes, int n_in,
                              void* d_out, int out_size) {
    const float* x    = (const float*)d_in[0];
    const void*  ei   = d_in[1];
    const float* Wl1  = (const float*)d_in[3];
    const float* bl1  = (const float*)d_in[4];
    const float* Wr1  = (const float*)d_in[5];
    const float* br1  = (const float*)d_in[6];
    const float* att1 = (const float*)d_in[7];
    const float* bo1  = (const float*)d_in[8];
    const float* Wl2  = (const float*)d_in[9];
    const float* bl2  = (const float*)d_in[10];
    const float* Wr2  = (const float*)d_in[11];
    const float* br2  = (const float*)d_in[12];
    const float* att2 = (const float*)d_in[13];
    const float* bo2  = (const float*)d_in[14];
    float* out = (float*)d_out;

    __half *p_xl1, *p_xr1, *p_xl2, *p_xr2;
    float  *p_h;
    cudaGetSymbolAddress((void**)&p_xl1, g_xl1h);
    cudaGetSymbolAddress((void**)&p_xr1, g_xr1h);
    cudaGetSymbolAddress((void**)&p_h,   g_h);
    cudaGetSymbolAddress((void**)&p_xl2, g_xl2h);
    cudaGetSymbolAddress((void**)&p_xr2, g_xr2h);

    const int nblk = (NN + 63) / 64;   // 1563

    detect_kernel<<<1, 32>>>(ei);
    convert_edges<<<(2 * EE + 255) / 256, 256>>>(ei);

    zero_deg_kernel<<<(NN + 255) / 256, 256>>>();
    hist_kernel<<<(NE_TOT + 255) / 256, 256>>>();
    scan_kernel<<<1, 1024>>>();
    scatter_kernel<<<(NE_TOT + 255) / 256, 256>>>();

    gemm_bias_h<<<dim3(nblk, 1), 256>>>(x, Wl1, bl1, p_xl1, NN, HC1);
    gemm_bias_h<<<dim3(nblk, 1), 256>>>(x, Wr1, br1, p_xr1, NN, HC1);

    edge1_node_kernel<<<(NN * 32 + 255) / 256, 256>>>(att1, bo1);

    gemm_bias_h<<<dim3(nblk, 4), 256>>>(p_h, Wl2, bl2, p_xl2, NN, HN2);
    gemm_bias_h<<<dim3(nblk, 4), 256>>>(p_h, Wr2, br2, p_xr2, NN, HN2);

    edge2_node_kernel<<<NN, 128>>>(att2, bo2, out);
}

// round 3
// speedup vs baseline: 2.6706x; 1.2399x over previous
#include <cuda_runtime.h>
#include <cuda_fp16.h>
#include <cstdint>

#define NN 100000
#define EE 1600000
#define NE_TOT (EE + NN)          // edges incl. self loops
#define H4 4
#define HC1 64                     // H*C1 (layer1 per-node feat)
#define NOUT 64
#define HN2 256                    // H*NOUT (layer2 per-node feat)
#define NEG_SLOPE 0.2f

// ---------------- scratch (device globals; no allocation allowed) ----------
__device__ __half g_xl1h[(size_t)NN * HC1];
__device__ __half g_xr1h[(size_t)NN * HC1];
__device__ float  g_h   [(size_t)NN * HC1];
__device__ __half g_xl2h[(size_t)NN * HN2];
__device__ __half g_xr2h[(size_t)NN * HN2];
__device__ int    g_eidx[2 * EE];
__device__ int    g_is64;
__device__ int    g_deg[NN];
__device__ int    g_rs [NN + 1];
__device__ int    g_cur[NN];
__device__ int    g_csr[NE_TOT];

// ---------------- edge-index dtype detection + normalization ---------------
__global__ void detect_kernel(const void* p) {
    if (threadIdx.x == 0 && blockIdx.x == 0) {
        const long long* q = (const long long*)p;
        int is64 = 1;
        for (int i = 0; i < 256; i++) {
            long long v = q[i];
            if (v < 0 || v >= NN) { is64 = 0; break; }
        }
        g_is64 = is64;
    }
}

// deg[i] starts at 1 (self loop); this kernel adds real-edge dst counts and
// converts int64 -> int32 in one pass.
__global__ void init_deg_kernel() {
    int i = blockIdx.x * blockDim.x + threadIdx.x;
    if (i < NN) g_deg[i] = 1;
}

__global__ void convert_hist_kernel(const void* p) {
    int idx = blockIdx.x * blockDim.x + threadIdx.x;
    if (idx >= 2 * EE) return;
    int v;
    if (g_is64) v = (int)((const long long*)p)[idx];
    else        v = ((const int*)p)[idx];
    g_eidx[idx] = v;
    if (idx >= EE) atomicAdd(g_deg + v, 1);
}

// single-block exclusive scan of g_deg -> g_rs, copy to g_cur
__global__ __launch_bounds__(1024) void scan_kernel() {
    const int CH = (NN + 1023) / 1024;     // 98
    int t = threadIdx.x;
    int lo = t * CH, hi = lo + CH; if (hi > NN) hi = NN;
    int s = 0;
    for (int k = lo; k < hi; k++) s += g_deg[k];
    __shared__ int sums[1024];
    sums[t] = s; __syncthreads();
    for (int off = 1; off < 1024; off <<= 1) {
        int v = (t >= off) ? sums[t - off] : 0;
        __syncthreads();
        sums[t] += v;
        __syncthreads();
    }
    int run = sums[t] - s;                 // exclusive prefix for this chunk
    for (int k = lo; k < hi; k++) {
        g_rs[k] = run; g_cur[k] = run;
        run += g_deg[k];
    }
    if (t == 1023) g_rs[NN] = sums[1023];
}

__global__ void scatter_kernel() {
    int idx = blockIdx.x * blockDim.x + threadIdx.x;
    if (idx >= NE_TOT) return;
    int s, d;
    if (idx < EE) { s = g_eidx[idx]; d = g_eidx[EE + idx]; }
    else          { s = idx - EE; d = s; }
    int pos = atomicAdd(g_cur + d, 1);
    g_csr[pos] = s;
}

// ---------------- GEMM: Y[n x M](half) = X[n x 64] @ W[64 x M] + B ---------
// 128x64 block tile, 256 threads, 8x4 thread tile.
__global__ __launch_bounds__(256) void gemm_bias_h(
    const float* __restrict__ X, const float* __restrict__ W,
    const float* __restrict__ B, __half* __restrict__ Y, int n, int M)
{
    __shared__ float xs[64][132];  // [k][row], padded
    __shared__ float ws[64][64];   // [k][m]
    const int n0 = blockIdx.x * 128;
    const int m0 = blockIdx.y * 64;
    const int tid = threadIdx.x;

    #pragma unroll
    for (int it = 0; it < 32; it++) {
        int idx = tid + it * 256;
        int k = idx & 63, r = idx >> 6;
        int node = n0 + r;
        xs[k][r] = (node < n) ? X[(size_t)node * 64 + k] : 0.f;
    }
    #pragma unroll
    for (int it = 0; it < 16; it++) {
        int idx = tid + it * 256;
        int mm = idx & 63, k = idx >> 6;
        ws[k][mm] = W[(size_t)k * M + m0 + mm];
    }
    __syncthreads();

    const int tx = tid & 15, ty = tid >> 4;   // tx: 16 col groups, ty: 16 row groups
    float acc[8][4] = {};
    #pragma unroll
    for (int k = 0; k < 64; k++) {
        float4 a0 = *(const float4*)&xs[k][ty * 8];
        float4 a1 = *(const float4*)&xs[k][ty * 8 + 4];
        float4 b  = *(const float4*)&ws[k][tx * 4];
        float av[8] = {a0.x, a0.y, a0.z, a0.w, a1.x, a1.y, a1.z, a1.w};
        #pragma unroll
        for (int i = 0; i < 8; i++) {
            acc[i][0] = fmaf(av[i], b.x, acc[i][0]);
            acc[i][1] = fmaf(av[i], b.y, acc[i][1]);
            acc[i][2] = fmaf(av[i], b.z, acc[i][2]);
            acc[i][3] = fmaf(av[i], b.w, acc[i][3]);
        }
    }
    float4 bb = *(const float4*)&B[m0 + tx * 4];
    #pragma unroll
    for (int i = 0; i < 8; i++) {
        int node = n0 + ty * 8 + i;
        if (node < n) {
            size_t off = (size_t)node * M + m0 + tx * 4;
            __half2 h0 = __floats2half2_rn(acc[i][0] + bb.x, acc[i][1] + bb.y);
            __half2 h1 = __floats2half2_rn(acc[i][2] + bb.z, acc[i][3] + bb.w);
            uint2 pk;
            pk.x = *(const unsigned*)&h0;
            pk.y = *(const unsigned*)&h1;
            *(uint2*)&Y[off] = pk;
        }
    }
}

__device__ __forceinline__ float lrelu(float v) { return v > 0.f ? v : NEG_SLOPE * v; }

// ---------------- layer-1: one warp per node (CSR, atomic-free) -------------
__global__ __launch_bounds__(256) void edge1_node_kernel(
    const float* __restrict__ att, const float* __restrict__ bo)
{
    int node = (blockIdx.x * 256 + threadIdx.x) >> 5;
    if (node >= NN) return;
    int lane = threadIdx.x & 31;
    int c0 = lane * 2;

    float2 xr = __half22float2(*(const __half2*)(g_xr1h + (size_t)node * HC1 + c0));
    float  a0 = att[c0], a1 = att[c0 + 1];

    float accx = 0.f, accy = 0.f, den = 0.f;
    int rs = g_rs[node], re = g_rs[node + 1];
    for (int base = rs; base < re; base += 32) {
        int m = re - base;
        int sj = (lane < m) ? g_csr[base + lane] : 0;
        int jmax = (m < 32) ? m : 32;
        int j = 0;
        for (; j + 1 < jmax; j += 2) {
            int s0 = __shfl_sync(0xffffffffu, sj, j);
            int s1 = __shfl_sync(0xffffffffu, sj, j + 1);
            float2 xlA = __half22float2(*(const __half2*)(g_xl1h + (size_t)s0 * HC1 + c0));
            float2 xlB = __half22float2(*(const __half2*)(g_xl1h + (size_t)s1 * HC1 + c0));
            float pA = fmaf(a0, lrelu(xlA.x + xr.x), a1 * lrelu(xlA.y + xr.y));
            float pB = fmaf(a0, lrelu(xlB.x + xr.x), a1 * lrelu(xlB.y + xr.y));
            pA += __shfl_xor_sync(0xffffffffu, pA, 4);
            pB += __shfl_xor_sync(0xffffffffu, pB, 4);
            pA += __shfl_xor_sync(0xffffffffu, pA, 2);
            pB += __shfl_xor_sync(0xffffffffu, pB, 2);
            pA += __shfl_xor_sync(0xffffffffu, pA, 1);
            pB += __shfl_xor_sync(0xffffffffu, pB, 1);
            float exA = __expf(pA);
            float exB = __expf(pB);
            accx = fmaf(exA, xlA.x, accx); accy = fmaf(exA, xlA.y, accy);
            accx = fmaf(exB, xlB.x, accx); accy = fmaf(exB, xlB.y, accy);
            den += exA + exB;
        }
        if (j < jmax) {
            int s0 = __shfl_sync(0xffffffffu, sj, j);
            float2 xlA = __half22float2(*(const __half2*)(g_xl1h + (size_t)s0 * HC1 + c0));
            float pA = fmaf(a0, lrelu(xlA.x + xr.x), a1 * lrelu(xlA.y + xr.y));
            pA += __shfl_xor_sync(0xffffffffu, pA, 4);
            pA += __shfl_xor_sync(0xffffffffu, pA, 2);
            pA += __shfl_xor_sync(0xffffffffu, pA, 1);
            float exA = __expf(pA);
            accx = fmaf(exA, xlA.x, accx); accy = fmaf(exA, xlA.y, accy);
            den += exA;
        }
    }
    float inv = 1.f / (den + 1e-16f);
    float v0 = accx * inv + bo[c0];
    float v1 = accy * inv + bo[c0 + 1];
    size_t o = (size_t)node * HC1 + c0;
    g_h[o]     = v0 > 0.f ? v0 : 0.f;
    g_h[o + 1] = v1 > 0.f ? v1 : 0.f;
}

// ---------------- layer-2: one warp per node, all 4 heads per warp ----------
// lane l covers channels [8l, 8l+8): head = l>>3, within-head base = (l&7)*8.
__device__ __forceinline__ void half8_to_f(const __half* p, float* f) {
    uint4 raw = *(const uint4*)p;
    const __half2* hp = (const __half2*)&raw;
    #pragma unroll
    for (int i = 0; i < 4; i++) {
        float2 t = __half22float2(hp[i]);
        f[2 * i] = t.x; f[2 * i + 1] = t.y;
    }
}

__global__ __launch_bounds__(256) void edge2_node_kernel(
    const float* __restrict__ att, const float* __restrict__ bo,
    float* __restrict__ out)
{
    int node = (blockIdx.x * 256 + threadIdx.x) >> 5;
    if (node >= NN) return;
    int lane = threadIdx.x & 31;
    int cb = lane * 8;               // channel base in [0,256)
    int cw = (lane & 7) * 8;         // within-head channel base

    float xr[8], a[8];
    half8_to_f(g_xr2h + (size_t)node * HN2 + cb, xr);
    float4 af0 = *(const float4*)(att + cb);
    float4 af1 = *(const float4*)(att + cb + 4);
    a[0] = af0.x; a[1] = af0.y; a[2] = af0.z; a[3] = af0.w;
    a[4] = af1.x; a[5] = af1.y; a[6] = af1.z; a[7] = af1.w;

    float acc[8] = {};
    float den = 0.f;
    int rs = g_rs[node], re = g_rs[node + 1];
    for (int base = rs; base < re; base += 32) {
        int m = re - base;
        int sj = (lane < m) ? g_csr[base + lane] : 0;
        int jmax = (m < 32) ? m : 32;
        int j = 0;
        for (; j + 1 < jmax; j += 2) {
            int s0 = __shfl_sync(0xffffffffu, sj, j);
            int s1 = __shfl_sync(0xffffffffu, sj, j + 1);
            float xlA[8], xlB[8];
            half8_to_f(g_xl2h + (size_t)s0 * HN2 + cb, xlA);
            half8_to_f(g_xl2h + (size_t)s1 * HN2 + cb, xlB);
            float pA = 0.f, pB = 0.f;
            #pragma unroll
            for (int k = 0; k < 8; k++) {
                pA = fmaf(a[k], lrelu(xlA[k] + xr[k]), pA);
                pB = fmaf(a[k], lrelu(xlB[k] + xr[k]), pB);
            }
            pA += __shfl_xor_sync(0xffffffffu, pA, 1);
            pB += __shfl_xor_sync(0xffffffffu, pB, 1);
            pA += __shfl_xor_sync(0xffffffffu, pA, 2);
            pB += __shfl_xor_sync(0xffffffffu, pB, 2);
            pA += __shfl_xor_sync(0xffffffffu, pA, 4);
            pB += __shfl_xor_sync(0xffffffffu, pB, 4);
            float exA = __expf(pA);
            float exB = __expf(pB);
            #pragma unroll
            for (int k = 0; k < 8; k++) {
                acc[k] = fmaf(exA, xlA[k], acc[k]);
                acc[k] = fmaf(exB, xlB[k], acc[k]);
            }
            den += exA + exB;
        }
        if (j < jmax) {
            int s0 = __shfl_sync(0xffffffffu, sj, j);
            float xlA[8];
            half8_to_f(g_xl2h + (size_t)s0 * HN2 + cb, xlA);
            float pA = 0.f;
            #pragma unroll
            for (int k = 0; k < 8; k++)
                pA = fmaf(a[k], lrelu(xlA[k] + xr[k]), pA);
            pA += __shfl_xor_sync(0xffffffffu, pA, 1);
            pA += __shfl_xor_sync(0xffffffffu, pA, 2);
            pA += __shfl_xor_sync(0xffffffffu, pA, 4);
            float exA = __expf(pA);
            #pragma unroll
            for (int k = 0; k < 8; k++)
                acc[k] = fmaf(exA, xlA[k], acc[k]);
            den += exA;
        }
    }
    float inv = 1.f / (den + 1e-16f);
    #pragma unroll
    for (int k = 0; k < 8; k++) {
        acc[k] *= inv;
        acc[k] += __shfl_xor_sync(0xffffffffu, acc[k], 8);
        acc[k] += __shfl_xor_sync(0xffffffffu, acc[k], 16);
    }
    if (lane < 8) {
        float4 o0, o1;
        float v;
        v = 0.25f * acc[0] + bo[cw + 0]; o0.x = v > 0.f ? v : 0.f;
        v = 0.25f * acc[1] + bo[cw + 1]; o0.y = v > 0.f ? v : 0.f;
        v = 0.25f * acc[2] + bo[cw + 2]; o0.z = v > 0.f ? v : 0.f;
        v = 0.25f * acc[3] + bo[cw + 3]; o0.w = v > 0.f ? v : 0.f;
        v = 0.25f * acc[4] + bo[cw + 4]; o1.x = v > 0.f ? v : 0.f;
        v = 0.25f * acc[5] + bo[cw + 5]; o1.y = v > 0.f ? v : 0.f;
        v = 0.25f * acc[6] + bo[cw + 6]; o1.z = v > 0.f ? v : 0.f;
        v = 0.25f * acc[7] + bo[cw + 7]; o1.w = v > 0.f ? v : 0.f;
        size_t off = (size_t)node * NOUT + cw;
        *(float4*)(out + off)     = o0;
        *(float4*)(out + off + 4) = o1;
    }
}

// ---------------- host orchestration ---------------------------------------
extern "C" void kernel_launch(void* const* d_in, const int* in_sizes, int n_in,
                              void* d_out, int out_size) {
    const float* x    = (const float*)d_in[0];
    const void*  ei   = d_in[1];
    const float* Wl1  = (const float*)d_in[3];
    const float* bl1  = (const float*)d_in[4];
    const float* Wr1  = (const float*)d_in[5];
    const float* br1  = (const float*)d_in[6];
    const float* att1 = (const float*)d_in[7];
    const float* bo1  = (const float*)d_in[8];
    const float* Wl2  = (const float*)d_in[9];
    const float* bl2  = (const float*)d_in[10];
    const float* Wr2  = (const float*)d_in[11];
    const float* br2  = (const float*)d_in[12];
    const float* att2 = (const float*)d_in[13];
    const float* bo2  = (const float*)d_in[14];
    float* out = (float*)d_out;

    __half *p_xl1, *p_xr1, *p_xl2, *p_xr2;
    float  *p_h;
    cudaGetSymbolAddress((void**)&p_xl1, g_xl1h);
    cudaGetSymbolAddress((void**)&p_xr1, g_xr1h);
    cudaGetSymbolAddress((void**)&p_h,   g_h);
    cudaGetSymbolAddress((void**)&p_xl2, g_xl2h);
    cudaGetSymbolAddress((void**)&p_xr2, g_xr2h);

    const int nblk = (NN + 127) / 128;   // 782

    detect_kernel<<<1, 32>>>(ei);
    init_deg_kernel<<<(NN + 255) / 256, 256>>>();
    convert_hist_kernel<<<(2 * EE + 255) / 256, 256>>>(ei);
    scan_kernel<<<1, 1024>>>();
    scatter_kernel<<<(NE_TOT + 255) / 256, 256>>>();

    gemm_bias_h<<<dim3(nblk, 1), 256>>>(x, Wl1, bl1, p_xl1, NN, HC1);
    gemm_bias_h<<<dim3(nblk, 1), 256>>>(x, Wr1, br1, p_xr1, NN, HC1);

    edge1_node_kernel<<<(NN * 32 + 255) / 256, 256>>>(att1, bo1);

    gemm_bias_h<<<dim3(nblk, 4), 256>>>(p_h, Wl2, bl2, p_xl2, NN, HN2);
    gemm_bias_h<<<dim3(nblk, 4), 256>>>(p_h, Wr2, br2, p_xr2, NN, HN2);

    edge2_node_kernel<<<(NN * 32 + 255) / 256, 256>>>(att2, bo2, out);
}

// round 4
// speedup vs baseline: 3.4859x; 1.3053x over previous
#include <cuda_runtime.h>
#include <cuda_fp16.h>
#include <cstdint>

#define NN 100000
#define EE 1600000
#define NE_TOT (EE + NN)          // edges incl. self loops
#define H4 4
#define HC1 64                     // H*C1 (layer1 per-node feat)
#define NOUT 64
#define HN2 256                    // H*NOUT (layer2 per-node feat)
#define NEG_SLOPE 0.2f

#define SCAN_CHUNK 2048
#define SCAN_NBLK ((NN + SCAN_CHUNK - 1) / SCAN_CHUNK)   // 49

// ---------------- scratch (device globals; no allocation allowed) ----------
__device__ __half g_xl1h[(size_t)NN * HC1];
__device__ __half g_xr1h[(size_t)NN * HC1];
__device__ float  g_h   [(size_t)NN * HC1];
__device__ __half g_xl2h[(size_t)NN * HN2];
__device__ __half g_xr2h[(size_t)NN * HN2];
__device__ int    g_eidx[2 * EE];
__device__ int    g_is64;
__device__ int    g_deg[NN];
__device__ int    g_rs [NN + 1];
__device__ int    g_cur[NN];
__device__ int    g_csr[NE_TOT];
__device__ int    g_bsum[SCAN_NBLK];
__device__ int    g_boff[SCAN_NBLK];

// ---------------- edge-index dtype detection + normalization ---------------
__global__ void detect_kernel(const void* p) {
    if (threadIdx.x == 0 && blockIdx.x == 0) {
        const long long* q = (const long long*)p;
        int is64 = 1;
        for (int i = 0; i < 256; i++) {
            long long v = q[i];
            if (v < 0 || v >= NN) { is64 = 0; break; }
        }
        g_is64 = is64;
    }
}

// deg[i] starts at 1 (self loop)
__global__ void init_deg_kernel() {
    int i = blockIdx.x * blockDim.x + threadIdx.x;
    if (i < NN) g_deg[i] = 1;
}

__global__ void convert_hist_kernel(const void* p) {
    int idx = blockIdx.x * blockDim.x + threadIdx.x;
    if (idx >= 2 * EE) return;
    int v;
    if (g_is64) v = (int)((const long long*)p)[idx];
    else        v = ((const int*)p)[idx];
    g_eidx[idx] = v;
    if (idx >= EE) atomicAdd(g_deg + v, 1);
}

// ---------------- parallel exclusive scan of g_deg --------------------------
// Phase 1: per-block sums (256 threads x 8 elems = 2048 per block)
__global__ __launch_bounds__(256) void scan_phase1() {
    int t = threadIdx.x;
    int base = blockIdx.x * SCAN_CHUNK + t * 8;
    int s = 0;
    #pragma unroll
    for (int k = 0; k < 8; k++) {
        int i = base + k;
        if (i < NN) s += g_deg[i];
    }
    // warp reduce
    #pragma unroll
    for (int off = 16; off; off >>= 1)
        s += __shfl_xor_sync(0xffffffffu, s, off);
    __shared__ int ws[8];
    if ((t & 31) == 0) ws[t >> 5] = s;
    __syncthreads();
    if (t == 0) {
        int tot = 0;
        #pragma unroll
        for (int w = 0; w < 8; w++) tot += ws[w];
        g_bsum[blockIdx.x] = tot;
    }
}

// Phase 2: scan the 49 block sums (1 warp, serial — tiny)
__global__ void scan_phase2() {
    if (threadIdx.x == 0) {
        int run = 0;
        for (int b = 0; b < SCAN_NBLK; b++) {
            g_boff[b] = run;
            run += g_bsum[b];
        }
        g_rs[NN] = run;
    }
}

// Phase 3: block-local exclusive scan + offset, write g_rs / g_cur
__global__ __launch_bounds__(256) void scan_phase3() {
    int t = threadIdx.x;
    int lane = t & 31, wid = t >> 5;
    int base = blockIdx.x * SCAN_CHUNK + t * 8;

    int d[8]; int s = 0;
    #pragma unroll
    for (int k = 0; k < 8; k++) {
        int i = base + k;
        d[k] = (i < NN) ? g_deg[i] : 0;
        s += d[k];
    }
    // inclusive warp scan of thread sums
    int inc = s;
    #pragma unroll
    for (int off = 1; off < 32; off <<= 1) {
        int v = __shfl_up_sync(0xffffffffu, inc, off);
        if (lane >= off) inc += v;
    }
    __shared__ int wtot[8];
    if (lane == 31) wtot[wid] = inc;
    __syncthreads();
    int woff = 0;
    #pragma unroll
    for (int w = 0; w < 8; w++) if (w < wid) woff += wtot[w];
    int run = g_boff[blockIdx.x] + woff + (inc - s);   // exclusive prefix
    #pragma unroll
    for (int k = 0; k < 8; k++) {
        int i = base + k;
        if (i < NN) { g_rs[i] = run; g_cur[i] = run; }
        run += d[k];
    }
}

__global__ void scatter_kernel() {
    int idx = blockIdx.x * blockDim.x + threadIdx.x;
    if (idx >= NE_TOT) return;
    int s, d;
    if (idx < EE) { s = g_eidx[idx]; d = g_eidx[EE + idx]; }
    else          { s = idx - EE; d = s; }
    int pos = atomicAdd(g_cur + d, 1);
    g_csr[pos] = s;
}

// ---------------- GEMM: Y[n x M](half) = X[n x 64] @ W[64 x M] + B ---------
// 128x64 block tile, 256 threads, 8x4 thread tile.
__global__ __launch_bounds__(256) void gemm_bias_h(
    const float* __restrict__ X, const float* __restrict__ W,
    const float* __restrict__ B, __half* __restrict__ Y, int n, int M)
{
    __shared__ float xs[64][132];  // [k][row], padded
    __shared__ float ws[64][64];   // [k][m]
    const int n0 = blockIdx.x * 128;
    const int m0 = blockIdx.y * 64;
    const int tid = threadIdx.x;

    #pragma unroll
    for (int it = 0; it < 32; it++) {
        int idx = tid + it * 256;
        int k = idx & 63, r = idx >> 6;
        int node = n0 + r;
        xs[k][r] = (node < n) ? X[(size_t)node * 64 + k] : 0.f;
    }
    #pragma unroll
    for (int it = 0; it < 16; it++) {
        int idx = tid + it * 256;
        int mm = idx & 63, k = idx >> 6;
        ws[k][mm] = W[(size_t)k * M + m0 + mm];
    }
    __syncthreads();

    const int tx = tid & 15, ty = tid >> 4;
    float acc[8][4] = {};
    #pragma unroll
    for (int k = 0; k < 64; k++) {
        float4 a0 = *(const float4*)&xs[k][ty * 8];
        float4 a1 = *(const float4*)&xs[k][ty * 8 + 4];
        float4 b  = *(const float4*)&ws[k][tx * 4];
        float av[8] = {a0.x, a0.y, a0.z, a0.w, a1.x, a1.y, a1.z, a1.w};
        #pragma unroll
        for (int i = 0; i < 8; i++) {
            acc[i][0] = fmaf(av[i], b.x, acc[i][0]);
            acc[i][1] = fmaf(av[i], b.y, acc[i][1]);
            acc[i][2] = fmaf(av[i], b.z, acc[i][2]);
            acc[i][3] = fmaf(av[i], b.w, acc[i][3]);
        }
    }
    float4 bb = *(const float4*)&B[m0 + tx * 4];
    #pragma unroll
    for (int i = 0; i < 8; i++) {
        int node = n0 + ty * 8 + i;
        if (node < n) {
            size_t off = (size_t)node * M + m0 + tx * 4;
            __half2 h0 = __floats2half2_rn(acc[i][0] + bb.x, acc[i][1] + bb.y);
            __half2 h1 = __floats2half2_rn(acc[i][2] + bb.z, acc[i][3] + bb.w);
            uint2 pk;
            pk.x = *(const unsigned*)&h0;
            pk.y = *(const unsigned*)&h1;
            *(uint2*)&Y[off] = pk;
        }
    }
}

__device__ __forceinline__ float lrelu(float v) { return v > 0.f ? v : NEG_SLOPE * v; }

// ---------------- layer-1: one warp per node (CSR, atomic-free) -------------
__global__ __launch_bounds__(256) void edge1_node_kernel(
    const float* __restrict__ att, const float* __restrict__ bo)
{
    int node = (blockIdx.x * 256 + threadIdx.x) >> 5;
    if (node >= NN) return;
    int lane = threadIdx.x & 31;
    int c0 = lane * 2;

    float2 xr = __half22float2(*(const __half2*)(g_xr1h + (size_t)node * HC1 + c0));
    float  a0 = att[c0], a1 = att[c0 + 1];

    float accx = 0.f, accy = 0.f, den = 0.f;
    int rs = g_rs[node], re = g_rs[node + 1];
    for (int base = rs; base < re; base += 32) {
        int m = re - base;
        int sj = (lane < m) ? g_csr[base + lane] : 0;
        int jmax = (m < 32) ? m : 32;
        int j = 0;
        for (; j + 1 < jmax; j += 2) {
            int s0 = __shfl_sync(0xffffffffu, sj, j);
            int s1 = __shfl_sync(0xffffffffu, sj, j + 1);
            float2 xlA = __half22float2(*(const __half2*)(g_xl1h + (size_t)s0 * HC1 + c0));
            float2 xlB = __half22float2(*(const __half2*)(g_xl1h + (size_t)s1 * HC1 + c0));
            float pA = fmaf(a0, lrelu(xlA.x + xr.x), a1 * lrelu(xlA.y + xr.y));
            float pB = fmaf(a0, lrelu(xlB.x + xr.x), a1 * lrelu(xlB.y + xr.y));
            pA += __shfl_xor_sync(0xffffffffu, pA, 4);
            pB += __shfl_xor_sync(0xffffffffu, pB, 4);
            pA += __shfl_xor_sync(0xffffffffu, pA, 2);
            pB += __shfl_xor_sync(0xffffffffu, pB, 2);
            pA += __shfl_xor_sync(0xffffffffu, pA, 1);
            pB += __shfl_xor_sync(0xffffffffu, pB, 1);
            float exA = __expf(pA);
            float exB = __expf(pB);
            accx = fmaf(exA, xlA.x, accx); accy = fmaf(exA, xlA.y, accy);
            accx = fmaf(exB, xlB.x, accx); accy = fmaf(exB, xlB.y, accy);
            den += exA + exB;
        }
        if (j < jmax) {
            int s0 = __shfl_sync(0xffffffffu, sj, j);
            float2 xlA = __half22float2(*(const __half2*)(g_xl1h + (size_t)s0 * HC1 + c0));
            float pA = fmaf(a0, lrelu(xlA.x + xr.x), a1 * lrelu(xlA.y + xr.y));
            pA += __shfl_xor_sync(0xffffffffu, pA, 4);
            pA += __shfl_xor_sync(0xffffffffu, pA, 2);
            pA += __shfl_xor_sync(0xffffffffu, pA, 1);
            float exA = __expf(pA);
            accx = fmaf(exA, xlA.x, accx); accy = fmaf(exA, xlA.y, accy);
            den += exA;
        }
    }
    float inv = 1.f / (den + 1e-16f);
    float v0 = accx * inv + bo[c0];
    float v1 = accy * inv + bo[c0 + 1];
    size_t o = (size_t)node * HC1 + c0;
    g_h[o]     = v0 > 0.f ? v0 : 0.f;
    g_h[o + 1] = v1 > 0.f ? v1 : 0.f;
}

// ---------------- layer-2: one warp per node, all 4 heads per warp ----------
__device__ __forceinline__ void half8_to_f(const __half* p, float* f) {
    uint4 raw = *(const uint4*)p;
    const __half2* hp = (const __half2*)&raw;
    #pragma unroll
    for (int i = 0; i < 4; i++) {
        float2 t = __half22float2(hp[i]);
        f[2 * i] = t.x; f[2 * i + 1] = t.y;
    }
}

__global__ __launch_bounds__(256) void edge2_node_kernel(
    const float* __restrict__ att, const float* __restrict__ bo,
    float* __restrict__ out)
{
    int node = (blockIdx.x * 256 + threadIdx.x) >> 5;
    if (node >= NN) return;
    int lane = threadIdx.x & 31;
    int cb = lane * 8;               // channel base in [0,256)
    int cw = (lane & 7) * 8;         // within-head channel base

    float xr[8], a[8];
    half8_to_f(g_xr2h + (size_t)node * HN2 + cb, xr);
    float4 af0 = *(const float4*)(att + cb);
    float4 af1 = *(const float4*)(att + cb + 4);
    a[0] = af0.x; a[1] = af0.y; a[2] = af0.z; a[3] = af0.w;
    a[4] = af1.x; a[5] = af1.y; a[6] = af1.z; a[7] = af1.w;

    float acc[8] = {};
    float den = 0.f;
    int rs = g_rs[node], re = g_rs[node + 1];
    for (int base = rs; base < re; base += 32) {
        int m = re - base;
        int sj = (lane < m) ? g_csr[base + lane] : 0;
        int jmax = (m < 32) ? m : 32;
        int j = 0;
        for (; j + 1 < jmax; j += 2) {
            int s0 = __shfl_sync(0xffffffffu, sj, j);
            int s1 = __shfl_sync(0xffffffffu, sj, j + 1);
            float xlA[8], xlB[8];
            half8_to_f(g_xl2h + (size_t)s0 * HN2 + cb, xlA);
            half8_to_f(g_xl2h + (size_t)s1 * HN2 + cb, xlB);
            float pA = 0.f, pB = 0.f;
            #pragma unroll
            for (int k = 0; k < 8; k++) {
                pA = fmaf(a[k], lrelu(xlA[k] + xr[k]), pA);
                pB = fmaf(a[k], lrelu(xlB[k] + xr[k]), pB);
            }
            pA += __shfl_xor_sync(0xffffffffu, pA, 1);
            pB += __shfl_xor_sync(0xffffffffu, pB, 1);
            pA += __shfl_xor_sync(0xffffffffu, pA, 2);
            pB += __shfl_xor_sync(0xffffffffu, pB, 2);
            pA += __shfl_xor_sync(0xffffffffu, pA, 4);
            pB += __shfl_xor_sync(0xffffffffu, pB, 4);
            float exA = __expf(pA);
            float exB = __expf(pB);
            #pragma unroll
            for (int k = 0; k < 8; k++) {
                acc[k] = fmaf(exA, xlA[k], acc[k]);
                acc[k] = fmaf(exB, xlB[k], acc[k]);
            }
            den += exA + exB;
        }
        if (j < jmax) {
            int s0 = __shfl_sync(0xffffffffu, sj, j);
            float xlA[8];
            half8_to_f(g_xl2h + (size_t)s0 * HN2 + cb, xlA);
            float pA = 0.f;
            #pragma unroll
            for (int k = 0; k < 8; k++)
                pA = fmaf(a[k], lrelu(xlA[k] + xr[k]), pA);
            pA += __shfl_xor_sync(0xffffffffu, pA, 1);
            pA += __shfl_xor_sync(0xffffffffu, pA, 2);
            pA += __shfl_xor_sync(0xffffffffu, pA, 4);
            float exA = __expf(pA);
            #pragma unroll
            for (int k = 0; k < 8; k++)
                acc[k] = fmaf(exA, xlA[k], acc[k]);
            den += exA;
        }
    }
    float inv = 1.f / (den + 1e-16f);
    #pragma unroll
    for (int k = 0; k < 8; k++) {
        acc[k] *= inv;
        acc[k] += __shfl_xor_sync(0xffffffffu, acc[k], 8);
        acc[k] += __shfl_xor_sync(0xffffffffu, acc[k], 16);
    }
    if (lane < 8) {
        float4 o0, o1;
        float v;
        v = 0.25f * acc[0] + bo[cw + 0]; o0.x = v > 0.f ? v : 0.f;
        v = 0.25f * acc[1] + bo[cw + 1]; o0.y = v > 0.f ? v : 0.f;
        v = 0.25f * acc[2] + bo[cw + 2]; o0.z = v > 0.f ? v : 0.f;
        v = 0.25f * acc[3] + bo[cw + 3]; o0.w = v > 0.f ? v : 0.f;
        v = 0.25f * acc[4] + bo[cw + 4]; o1.x = v > 0.f ? v : 0.f;
        v = 0.25f * acc[5] + bo[cw + 5]; o1.y = v > 0.f ? v : 0.f;
        v = 0.25f * acc[6] + bo[cw + 6]; o1.z = v > 0.f ? v : 0.f;
        v = 0.25f * acc[7] + bo[cw + 7]; o1.w = v > 0.f ? v : 0.f;
        size_t off = (size_t)node * NOUT + cw;
        *(float4*)(out + off)     = o0;
        *(float4*)(out + off + 4) = o1;
    }
}

// ---------------- host orchestration ---------------------------------------
extern "C" void kernel_launch(void* const* d_in, const int* in_sizes, int n_in,
                              void* d_out, int out_size) {
    const float* x    = (const float*)d_in[0];
    const void*  ei   = d_in[1];
    const float* Wl1  = (const float*)d_in[3];
    const float* bl1  = (const float*)d_in[4];
    const float* Wr1  = (const float*)d_in[5];
    const float* br1  = (const float*)d_in[6];
    const float* att1 = (const float*)d_in[7];
    const float* bo1  = (const float*)d_in[8];
    const float* Wl2  = (const float*)d_in[9];
    const float* bl2  = (const float*)d_in[10];
    const float* Wr2  = (const float*)d_in[11];
    const float* br2  = (const float*)d_in[12];
    const float* att2 = (const float*)d_in[13];
    const float* bo2  = (const float*)d_in[14];
    float* out = (float*)d_out;

    __half *p_xl1, *p_xr1, *p_xl2, *p_xr2;
    float  *p_h;
    cudaGetSymbolAddress((void**)&p_xl1, g_xl1h);
    cudaGetSymbolAddress((void**)&p_xr1, g_xr1h);
    cudaGetSymbolAddress((void**)&p_h,   g_h);
    cudaGetSymbolAddress((void**)&p_xl2, g_xl2h);
    cudaGetSymbolAddress((void**)&p_xr2, g_xr2h);

    const int nblk = (NN + 127) / 128;   // 782

    detect_kernel<<<1, 32>>>(ei);
    init_deg_kernel<<<(NN + 255) / 256, 256>>>();
    convert_hist_kernel<<<(2 * EE + 255) / 256, 256>>>(ei);
    scan_phase1<<<SCAN_NBLK, 256>>>();
    scan_phase2<<<1, 32>>>();
    scan_phase3<<<SCAN_NBLK, 256>>>();
    scatter_kernel<<<(NE_TOT + 255) / 256, 256>>>();

    gemm_bias_h<<<dim3(nblk, 1), 256>>>(x, Wl1, bl1, p_xl1, NN, HC1);
    gemm_bias_h<<<dim3(nblk, 1), 256>>>(x, Wr1, br1, p_xr1, NN, HC1);

    edge1_node_kernel<<<(NN * 32 + 255) / 256, 256>>>(att1, bo1);

    gemm_bias_h<<<dim3(nblk, 4), 256>>>(p_h, Wl2, bl2, p_xl2, NN, HN2);
    gemm_bias_h<<<dim3(nblk, 4), 256>>>(p_h, Wr2, br2, p_xr2, NN, HN2);

    edge2_node_kernel<<<(NN * 32 + 255) / 256, 256>>>(att2, bo2, out);
}

// round 5
// speedup vs baseline: 4.3434x; 1.2460x over previous
#include <cuda_runtime.h>
#include <cuda_fp16.h>
#include <cstdint>

#define NN 100000
#define EE 1600000
#define NE_TOT (EE + NN)          // edges incl. self loops
#define H4 4
#define HC1 64                     // H*C1 (layer1 per-node feat)
#define NOUT 64
#define HN2 256                    // H*NOUT (layer2 per-node feat)
#define NEG_SLOPE 0.2f

#define SCAN_CHUNK 2048
#define SCAN_NBLK ((NN + SCAN_CHUNK - 1) / SCAN_CHUNK)   // 49

// ---------------- scratch (device globals; no allocation allowed) ----------
__device__ __half g_xl1h[(size_t)NN * HC1];
__device__ __half g_xr1h[(size_t)NN * HC1];
__device__ float  g_h   [(size_t)NN * HC1];
__device__ __half g_xl2h[(size_t)NN * HN2];
__device__ __half g_xr2h[(size_t)NN * HN2];
__device__ int    g_eidx[2 * EE];
__device__ int    g_is64;
__device__ int    g_deg[NN];
__device__ int    g_rs [NN + 1];
__device__ int    g_cur[NN];
__device__ int    g_csr[NE_TOT];
__device__ int    g_bsum[SCAN_NBLK];
__device__ int    g_boff[SCAN_NBLK];

// ---------------- edge-index dtype detection + normalization ---------------
__global__ void detect_kernel(const void* p) {
    if (threadIdx.x == 0 && blockIdx.x == 0) {
        const long long* q = (const long long*)p;
        int is64 = 1;
        for (int i = 0; i < 256; i++) {
            long long v = q[i];
            if (v < 0 || v >= NN) { is64 = 0; break; }
        }
        g_is64 = is64;
    }
}

// deg[i] starts at 1 (self loop)
__global__ void init_deg_kernel() {
    int i = blockIdx.x * blockDim.x + threadIdx.x;
    if (i < NN) g_deg[i] = 1;
}

__global__ void convert_hist_kernel(const void* p) {
    int idx = blockIdx.x * blockDim.x + threadIdx.x;
    if (idx >= 2 * EE) return;
    int v;
    if (g_is64) v = (int)((const long long*)p)[idx];
    else        v = ((const int*)p)[idx];
    g_eidx[idx] = v;
    if (idx >= EE) atomicAdd(g_deg + v, 1);
}

// ---------------- parallel exclusive scan of g_deg --------------------------
__global__ __launch_bounds__(256) void scan_phase1() {
    int t = threadIdx.x;
    int base = blockIdx.x * SCAN_CHUNK + t * 8;
    int s = 0;
    #pragma unroll
    for (int k = 0; k < 8; k++) {
        int i = base + k;
        if (i < NN) s += g_deg[i];
    }
    #pragma unroll
    for (int off = 16; off; off >>= 1)
        s += __shfl_xor_sync(0xffffffffu, s, off);
    __shared__ int ws[8];
    if ((t & 31) == 0) ws[t >> 5] = s;
    __syncthreads();
    if (t == 0) {
        int tot = 0;
        #pragma unroll
        for (int w = 0; w < 8; w++) tot += ws[w];
        g_bsum[blockIdx.x] = tot;
    }
}

__global__ void scan_phase2() {
    if (threadIdx.x == 0) {
        int run = 0;
        for (int b = 0; b < SCAN_NBLK; b++) {
            g_boff[b] = run;
            run += g_bsum[b];
        }
        g_rs[NN] = run;
    }
}

__global__ __launch_bounds__(256) void scan_phase3() {
    int t = threadIdx.x;
    int lane = t & 31, wid = t >> 5;
    int base = blockIdx.x * SCAN_CHUNK + t * 8;

    int d[8]; int s = 0;
    #pragma unroll
    for (int k = 0; k < 8; k++) {
        int i = base + k;
        d[k] = (i < NN) ? g_deg[i] : 0;
        s += d[k];
    }
    int inc = s;
    #pragma unroll
    for (int off = 1; off < 32; off <<= 1) {
        int v = __shfl_up_sync(0xffffffffu, inc, off);
        if (lane >= off) inc += v;
    }
    __shared__ int wtot[8];
    if (lane == 31) wtot[wid] = inc;
    __syncthreads();
    int woff = 0;
    #pragma unroll
    for (int w = 0; w < 8; w++) if (w < wid) woff += wtot[w];
    int run = g_boff[blockIdx.x] + woff + (inc - s);
    #pragma unroll
    for (int k = 0; k < 8; k++) {
        int i = base + k;
        if (i < NN) { g_rs[i] = run; g_cur[i] = run; }
        run += d[k];
    }
}

__global__ void scatter_kernel() {
    int idx = blockIdx.x * blockDim.x + threadIdx.x;
    if (idx >= NE_TOT) return;
    int s, d;
    if (idx < EE) { s = g_eidx[idx]; d = g_eidx[EE + idx]; }
    else          { s = idx - EE; d = s; }
    int pos = atomicAdd(g_cur + d, 1);
    g_csr[pos] = s;
}

// ---------------- tensor-core GEMM (tf32 mma): Y(half) = X@W + B -----------
__device__ __forceinline__ unsigned f2tf32(float f) {
    unsigned u;
    asm("cvt.rna.tf32.f32 %0, %1;" : "=r"(u) : "f"(f));
    return u;
}

__device__ __forceinline__ void mma_tf32(float* c, const unsigned* a, const unsigned* b) {
    asm volatile(
        "mma.sync.aligned.m16n8k8.row.col.f32.tf32.tf32.f32 "
        "{%0,%1,%2,%3}, {%4,%5,%6,%7}, {%8,%9}, {%0,%1,%2,%3};\n"
        : "+f"(c[0]), "+f"(c[1]), "+f"(c[2]), "+f"(c[3])
        : "r"(a[0]), "r"(a[1]), "r"(a[2]), "r"(a[3]), "r"(b[0]), "r"(b[1]));
}

// Block: 256 threads (8 warps), tile 128 rows x 64 cols, K=64 (two 32-k phases).
__global__ __launch_bounds__(256) void gemm_tc_h(
    const float* __restrict__ X, const float* __restrict__ W,
    const float* __restrict__ Bi, __half* __restrict__ Y, int n, int M)
{
    __shared__ unsigned as_[128][36];   // [row][k-in-half], bank=(4r+c) conflict-free
    __shared__ unsigned bs[64][72];     // [k][col], bank=(8k+c) conflict-free
    const int n0 = blockIdx.x * 128;
    const int m0 = blockIdx.y * 64;
    const int tid = threadIdx.x;
    const int lane = tid & 31, w = tid >> 5;
    const int wr = w >> 1, wc = w & 1;      // 4 row-groups x 2 col-groups
    const int l4 = lane >> 2, lm4 = lane & 3;

    // load full B tile 64x64 once
    #pragma unroll
    for (int it = 0; it < 4; it++) {
        int idx = tid + it * 256;
        int k = idx >> 4, c4 = (idx & 15) * 4;
        float4 v = *(const float4*)&W[(size_t)k * M + m0 + c4];
        bs[k][c4]     = f2tf32(v.x);
        bs[k][c4 + 1] = f2tf32(v.y);
        bs[k][c4 + 2] = f2tf32(v.z);
        bs[k][c4 + 3] = f2tf32(v.w);
    }

    float c[2][4][4];
    #pragma unroll
    for (int mi = 0; mi < 2; mi++)
        #pragma unroll
        for (int ni = 0; ni < 4; ni++)
            #pragma unroll
            for (int q = 0; q < 4; q++) c[mi][ni][q] = 0.f;

    #pragma unroll
    for (int half = 0; half < 2; half++) {
        if (half) __syncthreads();
        #pragma unroll
        for (int it = 0; it < 4; it++) {
            int idx = tid + it * 256;
            int r = idx >> 3, c4 = (idx & 7) * 4;
            float4 v;
            if (n0 + r < n) v = *(const float4*)&X[(size_t)(n0 + r) * 64 + half * 32 + c4];
            else            v = make_float4(0.f, 0.f, 0.f, 0.f);
            as_[r][c4]     = f2tf32(v.x);
            as_[r][c4 + 1] = f2tf32(v.y);
            as_[r][c4 + 2] = f2tf32(v.z);
            as_[r][c4 + 3] = f2tf32(v.w);
        }
        __syncthreads();
        #pragma unroll
        for (int kk = 0; kk < 4; kk++) {
            int k0 = kk * 8;
            int kg = half * 32 + k0;
            unsigned a[2][4], b[4][2];
            #pragma unroll
            for (int mi = 0; mi < 2; mi++) {
                int rb = wr * 32 + mi * 16;
                a[mi][0] = as_[rb + l4][k0 + lm4];
                a[mi][1] = as_[rb + 8 + l4][k0 + lm4];
                a[mi][2] = as_[rb + l4][k0 + 4 + lm4];
                a[mi][3] = as_[rb + 8 + l4][k0 + 4 + lm4];
            }
            #pragma unroll
            for (int ni = 0; ni < 4; ni++) {
                int cb = wc * 32 + ni * 8;
                b[ni][0] = bs[kg + lm4][cb + l4];
                b[ni][1] = bs[kg + 4 + lm4][cb + l4];
            }
            #pragma unroll
            for (int mi = 0; mi < 2; mi++)
                #pragma unroll
                for (int ni = 0; ni < 4; ni++)
                    mma_tf32(c[mi][ni], a[mi], b[ni]);
        }
    }

    // epilogue: +bias, half2 store
    #pragma unroll
    for (int mi = 0; mi < 2; mi++) {
        #pragma unroll
        for (int rr = 0; rr < 2; rr++) {
            int node = n0 + wr * 32 + mi * 16 + rr * 8 + l4;
            if (node < n) {
                #pragma unroll
                for (int ni = 0; ni < 4; ni++) {
                    int col = wc * 32 + ni * 8 + 2 * lm4;
                    float v0 = c[mi][ni][rr * 2 + 0] + Bi[m0 + col];
                    float v1 = c[mi][ni][rr * 2 + 1] + Bi[m0 + col + 1];
                    __half2 hh = __floats2half2_rn(v0, v1);
                    *(__half2*)&Y[(size_t)node * M + m0 + col] = hh;
                }
            }
        }
    }
}

__device__ __forceinline__ float lrelu(float v) { return v > 0.f ? v : NEG_SLOPE * v; }

// ---------------- layer-1: one warp per node (CSR, atomic-free) -------------
__global__ __launch_bounds__(256) void edge1_node_kernel(
    const float* __restrict__ att, const float* __restrict__ bo)
{
    int node = (blockIdx.x * 256 + threadIdx.x) >> 5;
    if (node >= NN) return;
    int lane = threadIdx.x & 31;
    int c0 = lane * 2;

    float2 xr = __half22float2(*(const __half2*)(g_xr1h + (size_t)node * HC1 + c0));
    float  a0 = att[c0], a1 = att[c0 + 1];

    float accx = 0.f, accy = 0.f, den = 0.f;
    int rs = g_rs[node], re = g_rs[node + 1];
    for (int base = rs; base < re; base += 32) {
        int m = re - base;
        int sj = (lane < m) ? g_csr[base + lane] : 0;
        int jmax = (m < 32) ? m : 32;
        int j = 0;
        for (; j + 1 < jmax; j += 2) {
            int s0 = __shfl_sync(0xffffffffu, sj, j);
            int s1 = __shfl_sync(0xffffffffu, sj, j + 1);
            float2 xlA = __half22float2(*(const __half2*)(g_xl1h + (size_t)s0 * HC1 + c0));
            float2 xlB = __half22float2(*(const __half2*)(g_xl1h + (size_t)s1 * HC1 + c0));
            float pA = fmaf(a0, lrelu(xlA.x + xr.x), a1 * lrelu(xlA.y + xr.y));
            float pB = fmaf(a0, lrelu(xlB.x + xr.x), a1 * lrelu(xlB.y + xr.y));
            pA += __shfl_xor_sync(0xffffffffu, pA, 4);
            pB += __shfl_xor_sync(0xffffffffu, pB, 4);
            pA += __shfl_xor_sync(0xffffffffu, pA, 2);
            pB += __shfl_xor_sync(0xffffffffu, pB, 2);
            pA += __shfl_xor_sync(0xffffffffu, pA, 1);
            pB += __shfl_xor_sync(0xffffffffu, pB, 1);
            float exA = __expf(pA);
            float exB = __expf(pB);
            accx = fmaf(exA, xlA.x, accx); accy = fmaf(exA, xlA.y, accy);
            accx = fmaf(exB, xlB.x, accx); accy = fmaf(exB, xlB.y, accy);
            den += exA + exB;
        }
        if (j < jmax) {
            int s0 = __shfl_sync(0xffffffffu, sj, j);
            float2 xlA = __half22float2(*(const __half2*)(g_xl1h + (size_t)s0 * HC1 + c0));
            float pA = fmaf(a0, lrelu(xlA.x + xr.x), a1 * lrelu(xlA.y + xr.y));
            pA += __shfl_xor_sync(0xffffffffu, pA, 4);
            pA += __shfl_xor_sync(0xffffffffu, pA, 2);
            pA += __shfl_xor_sync(0xffffffffu, pA, 1);
            float exA = __expf(pA);
            accx = fmaf(exA, xlA.x, accx); accy = fmaf(exA, xlA.y, accy);
            den += exA;
        }
    }
    float inv = 1.f / (den + 1e-16f);
    float v0 = accx * inv + bo[c0];
    float v1 = accy * inv + bo[c0 + 1];
    size_t o = (size_t)node * HC1 + c0;
    g_h[o]     = v0 > 0.f ? v0 : 0.f;
    g_h[o + 1] = v1 > 0.f ? v1 : 0.f;
}

// ---------------- layer-2: one warp per node, all 4 heads per warp ----------
__device__ __forceinline__ void half8_to_f(const __half* p, float* f) {
    uint4 raw = *(const uint4*)p;
    const __half2* hp = (const __half2*)&raw;
    #pragma unroll
    for (int i = 0; i < 4; i++) {
        float2 t = __half22float2(hp[i]);
        f[2 * i] = t.x; f[2 * i + 1] = t.y;
    }
}

__global__ __launch_bounds__(256) void edge2_node_kernel(
    const float* __restrict__ att, const float* __restrict__ bo,
    float* __restrict__ out)
{
    int node = (blockIdx.x * 256 + threadIdx.x) >> 5;
    if (node >= NN) return;
    int lane = threadIdx.x & 31;
    int cb = lane * 8;
    int cw = (lane & 7) * 8;

    float xr[8], a[8];
    half8_to_f(g_xr2h + (size_t)node * HN2 + cb, xr);
    float4 af0 = *(const float4*)(att + cb);
    float4 af1 = *(const float4*)(att + cb + 4);
    a[0] = af0.x; a[1] = af0.y; a[2] = af0.z; a[3] = af0.w;
    a[4] = af1.x; a[5] = af1.y; a[6] = af1.z; a[7] = af1.w;

    float acc[8] = {};
    float den = 0.f;
    int rs = g_rs[node], re = g_rs[node + 1];
    for (int base = rs; base < re; base += 32) {
        int m = re - base;
        int sj = (lane < m) ? g_csr[base + lane] : 0;
        int jmax = (m < 32) ? m : 32;
        int j = 0;
        for (; j + 1 < jmax; j += 2) {
            int s0 = __shfl_sync(0xffffffffu, sj, j);
            int s1 = __shfl_sync(0xffffffffu, sj, j + 1);
            float xlA[8], xlB[8];
            half8_to_f(g_xl2h + (size_t)s0 * HN2 + cb, xlA);
            half8_to_f(g_xl2h + (size_t)s1 * HN2 + cb, xlB);
            float pA = 0.f, pB = 0.f;
            #pragma unroll
            for (int k = 0; k < 8; k++) {
                pA = fmaf(a[k], lrelu(xlA[k] + xr[k]), pA);
                pB = fmaf(a[k], lrelu(xlB[k] + xr[k]), pB);
            }
            pA += __shfl_xor_sync(0xffffffffu, pA, 1);
            pB += __shfl_xor_sync(0xffffffffu, pB, 1);
            pA += __shfl_xor_sync(0xffffffffu, pA, 2);
            pB += __shfl_xor_sync(0xffffffffu, pB, 2);
            pA += __shfl_xor_sync(0xffffffffu, pA, 4);
            pB += __shfl_xor_sync(0xffffffffu, pB, 4);
            float exA = __expf(pA);
            float exB = __expf(pB);
            #pragma unroll
            for (int k = 0; k < 8; k++) {
                acc[k] = fmaf(exA, xlA[k], acc[k]);
                acc[k] = fmaf(exB, xlB[k], acc[k]);
            }
            den += exA + exB;
        }
        if (j < jmax) {
            int s0 = __shfl_sync(0xffffffffu, sj, j);
            float xlA[8];
            half8_to_f(g_xl2h + (size_t)s0 * HN2 + cb, xlA);
            float pA = 0.f;
            #pragma unroll
            for (int k = 0; k < 8; k++)
                pA = fmaf(a[k], lrelu(xlA[k] + xr[k]), pA);
            pA += __shfl_xor_sync(0xffffffffu, pA, 1);
            pA += __shfl_xor_sync(0xffffffffu, pA, 2);
            pA += __shfl_xor_sync(0xffffffffu, pA, 4);
            float exA = __expf(pA);
            #pragma unroll
            for (int k = 0; k < 8; k++)
                acc[k] = fmaf(exA, xlA[k], acc[k]);
            den += exA;
        }
    }
    float inv = 1.f / (den + 1e-16f);
    #pragma unroll
    for (int k = 0; k < 8; k++) {
        acc[k] *= inv;
        acc[k] += __shfl_xor_sync(0xffffffffu, acc[k], 8);
        acc[k] += __shfl_xor_sync(0xffffffffu, acc[k], 16);
    }
    if (lane < 8) {
        float4 o0, o1;
        float v;
        v = 0.25f * acc[0] + bo[cw + 0]; o0.x = v > 0.f ? v : 0.f;
        v = 0.25f * acc[1] + bo[cw + 1]; o0.y = v > 0.f ? v : 0.f;
        v = 0.25f * acc[2] + bo[cw + 2]; o0.z = v > 0.f ? v : 0.f;
        v = 0.25f * acc[3] + bo[cw + 3]; o0.w = v > 0.f ? v : 0.f;
        v = 0.25f * acc[4] + bo[cw + 4]; o1.x = v > 0.f ? v : 0.f;
        v = 0.25f * acc[5] + bo[cw + 5]; o1.y = v > 0.f ? v : 0.f;
        v = 0.25f * acc[6] + bo[cw + 6]; o1.z = v > 0.f ? v : 0.f;
        v = 0.25f * acc[7] + bo[cw + 7]; o1.w = v > 0.f ? v : 0.f;
        size_t off = (size_t)node * NOUT + cw;
        *(float4*)(out + off)     = o0;
        *(float4*)(out + off + 4) = o1;
    }
}

// ---------------- host orchestration ---------------------------------------
extern "C" void kernel_launch(void* const* d_in, const int* in_sizes, int n_in,
                              void* d_out, int out_size) {
    const float* x    = (const float*)d_in[0];
    const void*  ei   = d_in[1];
    const float* Wl1  = (const float*)d_in[3];
    const float* bl1  = (const float*)d_in[4];
    const float* Wr1  = (const float*)d_in[5];
    const float* br1  = (const float*)d_in[6];
    const float* att1 = (const float*)d_in[7];
    const float* bo1  = (const float*)d_in[8];
    const float* Wl2  = (const float*)d_in[9];
    const float* bl2  = (const float*)d_in[10];
    const float* Wr2  = (const float*)d_in[11];
    const float* br2  = (const float*)d_in[12];
    const float* att2 = (const float*)d_in[13];
    const float* bo2  = (const float*)d_in[14];
    float* out = (float*)d_out;

    __half *p_xl1, *p_xr1, *p_xl2, *p_xr2;
    float  *p_h;
    cudaGetSymbolAddress((void**)&p_xl1, g_xl1h);
    cudaGetSymbolAddress((void**)&p_xr1, g_xr1h);
    cudaGetSymbolAddress((void**)&p_h,   g_h);
    cudaGetSymbolAddress((void**)&p_xl2, g_xl2h);
    cudaGetSymbolAddress((void**)&p_xr2, g_xr2h);

    const int nblk = (NN + 127) / 128;   // 782

    detect_kernel<<<1, 32>>>(ei);
    init_deg_kernel<<<(NN + 255) / 256, 256>>>();
    convert_hist_kernel<<<(2 * EE + 255) / 256, 256>>>(ei);
    scan_phase1<<<SCAN_NBLK, 256>>>();
    scan_phase2<<<1, 32>>>();
    scan_phase3<<<SCAN_NBLK, 256>>>();
    scatter_kernel<<<(NE_TOT + 255) / 256, 256>>>();

    gemm_tc_h<<<dim3(nblk, 1), 256>>>(x, Wl1, bl1, p_xl1, NN, HC1);
    gemm_tc_h<<<dim3(nblk, 1), 256>>>(x, Wr1, br1, p_xr1, NN, HC1);

    edge1_node_kernel<<<(NN * 32 + 255) / 256, 256>>>(att1, bo1);

    gemm_tc_h<<<dim3(nblk, 4), 256>>>(p_h, Wl2, bl2, p_xl2, NN, HN2);
    gemm_tc_h<<<dim3(nblk, 4), 256>>>(p_h, Wr2, br2, p_xr2, NN, HN2);

    edge2_node_kernel<<<(NN * 32 + 255) / 256, 256>>>(att2, bo2, out);
}